// round 10
// baseline (speedup 1.0000x reference)
#include <cuda_runtime.h>
#include <math.h>

#define IMG_H 512
#define IMG_W 512
#define NB    64
#define NPIX  (IMG_H * IMG_W)
#define NPEL  (NPIX * 3)
#define RBLK  32
#define ROWF  (IMG_W * 3)

__device__ float g_scratch[(size_t)NB * NPEL];
__device__ float g_partial0[NB * RBLK];
__device__ float g_partial1[NB * RBLK];

struct F3 { float x, y, z; };

__device__ __forceinline__ float inline_mean(const float* __restrict__ part, int b)
{
    float s = 0.f;
    #pragma unroll
    for (int i = 0; i < RBLK; i++) s += part[b * RBLK + i];
    return s * (1.0f / (float)NPEL);
}

// ---------------------------------------------------------------------------
// horizontal 2-tap bilinear (wy == 0 exactly)
// ---------------------------------------------------------------------------
__device__ __forceinline__ F3 bilin_h(const float* __restrict__ img, float xi, int y)
{
    float x0f = floorf(xi);
    float wx  = xi - x0f;
    float w0  = 1.f - wx;
    int   x0  = (int)x0f;
    const float* row = img + (size_t)y * ROWF;
    F3 r;
    if (x0 >= 0 && x0 < IMG_W - 1) {
        const float* p = row + x0 * 3;
        r.x = w0 * p[0] + wx * p[3];
        r.y = w0 * p[1] + wx * p[4];
        r.z = w0 * p[2] + wx * p[5];
    } else {
        bool v0 = (x0 >= 0)  && (x0 <= IMG_W - 1);
        bool v1 = (x0 >= -1) && (x0 <= IMG_W - 2);
        int xc0 = min(max(x0,     0), IMG_W - 1);
        int xc1 = min(max(x0 + 1, 0), IMG_W - 1);
        const float* p0 = row + xc0 * 3;
        const float* p1 = row + xc1 * 3;
        float a0 = v0 ? p0[0] : 0.5f, a1 = v0 ? p0[1] : 0.5f, a2 = v0 ? p0[2] : 0.5f;
        float b0 = v1 ? p1[0] : 0.5f, b1 = v1 ? p1[1] : 0.5f, b2 = v1 ? p1[2] : 0.5f;
        r.x = w0 * a0 + wx * b0;
        r.y = w0 * a1 + wx * b1;
        r.z = w0 * a2 + wx * b2;
    }
    return r;
}

// ---------------------------------------------------------------------------
// vertical 2-tap bilinear, single output (border/fallback)
// ---------------------------------------------------------------------------
__device__ __forceinline__ F3 bilin_v(const float* __restrict__ img, float yi, int x)
{
    float y0f = floorf(yi);
    float wy  = yi - y0f;
    float w0  = 1.f - wy;
    int   y0  = (int)y0f;
    F3 r;
    if (y0 >= 0 && y0 < IMG_H - 1) {
        const float* p = img + ((size_t)y0 * IMG_W + x) * 3;
        const float* q = p + ROWF;
        r.x = w0 * p[0] + wy * q[0];
        r.y = w0 * p[1] + wy * q[1];
        r.z = w0 * p[2] + wy * q[2];
    } else {
        bool v0 = (y0 >= 0)  && (y0 <= IMG_H - 1);
        bool v1 = (y0 >= -1) && (y0 <= IMG_H - 2);
        int yc0 = min(max(y0,     0), IMG_H - 1);
        int yc1 = min(max(y0 + 1, 0), IMG_H - 1);
        const float* p0 = img + ((size_t)yc0 * IMG_W + x) * 3;
        const float* p1 = img + ((size_t)yc1 * IMG_W + x) * 3;
        float a0 = v0 ? p0[0] : 0.5f, a1 = v0 ? p0[1] : 0.5f, a2 = v0 ? p0[2] : 0.5f;
        float b0 = v1 ? p1[0] : 0.5f, b1 = v1 ? p1[1] : 0.5f, b2 = v1 ? p1[2] : 0.5f;
        r.x = w0 * a0 + wy * b0;
        r.y = w0 * a1 + wy * b1;
        r.z = w0 * a2 + wy * b2;
    }
    return r;
}

// ---------------------------------------------------------------------------
// quad-row vertical bilinear: yi[i] for rows y..y+3 at column x.
// Shared path when floor(yi[i]) == floor(yi[0])+i: 5 tap rows for 4 outputs.
// ---------------------------------------------------------------------------
__device__ __forceinline__ void bilin_v4(const float* __restrict__ img,
                                         const float yi[4], int x, F3 r[4])
{
    float k0f = floorf(yi[0]);
    int   k0  = (int)k0f;
    bool aligned = (k0 >= 0) && (k0 + 4 <= IMG_H - 1);
    #pragma unroll
    for (int i = 1; i < 4; i++)
        aligned = aligned && ((int)floorf(yi[i]) == k0 + i);
    if (aligned) {
        const float* p = img + ((size_t)k0 * IMG_W + x) * 3;
        float rv[5][3];
        #pragma unroll
        for (int j = 0; j < 5; j++) {
            rv[j][0] = p[0]; rv[j][1] = p[1]; rv[j][2] = p[2];
            p += ROWF;
        }
        #pragma unroll
        for (int i = 0; i < 4; i++) {
            float wy = yi[i] - floorf(yi[i]);
            float w0 = 1.f - wy;
            r[i].x = w0 * rv[i][0] + wy * rv[i+1][0];
            r[i].y = w0 * rv[i][1] + wy * rv[i+1][1];
            r[i].z = w0 * rv[i][2] + wy * rv[i+1][2];
        }
    } else {
        #pragma unroll
        for (int i = 0; i < 4; i++) r[i] = bilin_v(img, yi[i], x);
    }
}

// ---------------------------------------------------------------------------
// general 4-tap bilinear (rotate)
// ---------------------------------------------------------------------------
__device__ __forceinline__ F3 bilin4(const float* __restrict__ img, float xi, float yi)
{
    float x0f = floorf(xi), y0f = floorf(yi);
    float wx = xi - x0f,    wy = yi - y0f;
    int   x0 = (int)x0f,    y0 = (int)y0f;
    float w00 = (1.f - wx) * (1.f - wy);
    float w10 = wx * (1.f - wy);
    float w01 = (1.f - wx) * wy;
    float w11 = wx * wy;
    F3 r;
    if (x0 >= 0 && x0 < IMG_W - 1 && y0 >= 0 && y0 < IMG_H - 1) {
        const float* p = img + ((size_t)y0 * IMG_W + x0) * 3;
        const float* q = p + ROWF;
        r.x = w00 * p[0] + w10 * p[3] + w01 * q[0] + w11 * q[3];
        r.y = w00 * p[1] + w10 * p[4] + w01 * q[1] + w11 * q[4];
        r.z = w00 * p[2] + w10 * p[5] + w01 * q[2] + w11 * q[5];
    } else {
        bool vx0 = (x0 >= 0)  && (x0 <= IMG_W - 1);
        bool vx1 = (x0 >= -1) && (x0 <= IMG_W - 2);
        bool vy0 = (y0 >= 0)  && (y0 <= IMG_H - 1);
        bool vy1 = (y0 >= -1) && (y0 <= IMG_H - 2);
        int xc0 = min(max(x0,     0), IMG_W - 1);
        int xc1 = min(max(x0 + 1, 0), IMG_W - 1);
        int yc0 = min(max(y0,     0), IMG_H - 1);
        int yc1 = min(max(y0 + 1, 0), IMG_H - 1);
        const float* p00 = img + ((size_t)yc0 * IMG_W + xc0) * 3;
        const float* p10 = img + ((size_t)yc0 * IMG_W + xc1) * 3;
        const float* p01 = img + ((size_t)yc1 * IMG_W + xc0) * 3;
        const float* p11 = img + ((size_t)yc1 * IMG_W + xc1) * 3;
        bool v00 = vx0 && vy0, v10 = vx1 && vy0, v01 = vx0 && vy1, v11 = vx1 && vy1;
        r.x = w00 * (v00 ? p00[0] : 0.5f) + w10 * (v10 ? p10[0] : 0.5f)
            + w01 * (v01 ? p01[0] : 0.5f) + w11 * (v11 ? p11[0] : 0.5f);
        r.y = w00 * (v00 ? p00[1] : 0.5f) + w10 * (v10 ? p10[1] : 0.5f)
            + w01 * (v01 ? p01[1] : 0.5f) + w11 * (v11 ? p11[1] : 0.5f);
        r.z = w00 * (v00 ? p00[2] : 0.5f) + w10 * (v10 ? p10[2] : 0.5f)
            + w01 * (v01 ? p01[2] : 0.5f) + w11 * (v11 ? p11[2] : 0.5f);
    }
    return r;
}

// ---------------------------------------------------------------------------
// single-pixel sharpness (border/fallback)
// ---------------------------------------------------------------------------
__device__ __forceinline__ F3 sharp3x3(const float* __restrict__ img,
                                       float f, int x, int y)
{
    const float* p = img + ((size_t)y * IMG_W + x) * 3;
    float v0 = p[0], v1 = p[1], v2 = p[2];
    float s0 = 0.f, s1 = 0.f, s2 = 0.f;
    #pragma unroll
    for (int dy = -1; dy <= 1; dy++) {
        int yy = min(max(y + dy, 0), IMG_H - 1);
        #pragma unroll
        for (int dx = -1; dx <= 1; dx++) {
            int xx = min(max(x + dx, 0), IMG_W - 1);
            float k = (dx == 0 && dy == 0) ? (5.0f/13.0f) : (1.0f/13.0f);
            const float* q = img + ((size_t)yy * IMG_W + xx) * 3;
            s0 += k * q[0]; s1 += k * q[1]; s2 += k * q[2];
        }
    }
    F3 r;
    r.x = fminf(fmaxf(s0 + f * (v0 - s0), 0.f), 1.f);
    r.y = fminf(fmaxf(s1 + f * (v1 - s1), 0.f), 1.f);
    r.z = fminf(fmaxf(s2 + f * (v2 - s2), 0.f), 1.f);
    return r;
}

// ---------------------------------------------------------------------------
// quad-row sharpness: outputs for rows y..y+3. Interior loads 6 kernel rows
// (18 taps) for 4 outputs; processed channel-at-a-time to bound registers.
// ---------------------------------------------------------------------------
__device__ __forceinline__ void sharp4(const float* __restrict__ img,
                                       float f, int x, int y, F3 r[4])
{
    if (x >= 1 && x <= IMG_W - 2 && y >= 1 && y + 4 <= IMG_H - 1) {
        const float* base = img + ((size_t)(y - 1) * IMG_W + x) * 3;
        float out[4][3];
        #pragma unroll
        for (int ch = 0; ch < 3; ch++) {
            float R[6], V[6];
            #pragma unroll
            for (int j = 0; j < 6; j++) {
                const float* p = base + (size_t)j * ROWF;
                float l = p[ch - 3], c = p[ch], rr = p[ch + 3];
                V[j] = c;
                R[j] = l + c + rr;
            }
            #pragma unroll
            for (int i = 0; i < 4; i++) {
                float v = V[i + 1];
                float s = (R[i] + R[i+1] + R[i+2] + 4.f * v) * (1.f / 13.f);
                out[i][ch] = fminf(fmaxf(s + f * (v - s), 0.f), 1.f);
            }
        }
        #pragma unroll
        for (int i = 0; i < 4; i++) {
            r[i].x = out[i][0]; r[i].y = out[i][1]; r[i].z = out[i][2];
        }
    } else {
        #pragma unroll
        for (int i = 0; i < 4; i++) r[i] = sharp3x3(img, f, x, y + i);
    }
}

// ---------------------------------------------------------------------------
// quad-row gather dispatch; op image-uniform, pixels (x, y..y+3)
// ---------------------------------------------------------------------------
__device__ __forceinline__ void apply_gather4(const float* __restrict__ img,
                                              int op, float s, int x, int y,
                                              F3 r[4])
{
    const float cx = (IMG_W - 1) * 0.5f, cy = (IMG_H - 1) * 0.5f;
    const float xf = (float)x - cx;
    float yf[4];
    #pragma unroll
    for (int i = 0; i < 4; i++) yf[i] = (float)(y + i) - cy;

    if (op == 0) {                              // rotate
        float th = s * 0.2617993877991494f;
        float co = cosf(th), si = sinf(th);
        #pragma unroll
        for (int i = 0; i < 4; i++)
            r[i] = bilin4(img, co * xf + si * yf[i] + cx,
                               -si * xf + co * yf[i] + cy);
    } else if (op == 1) {                       // shear_x
        float sh = -s * 0.15f;
        #pragma unroll
        for (int i = 0; i < 4; i++)
            r[i] = bilin_h(img, xf + sh * yf[i] + cx, y + i);
    } else if (op == 2) {                       // shear_y
        float sh = -s * 0.15f;
        float yi[4];
        #pragma unroll
        for (int i = 0; i < 4; i++) yi[i] = yf[i] + sh * xf + cy;
        bilin_v4(img, yi, x, r);
    } else if (op == 3) {                       // trans_x
        float t = -s * 0.15f * (float)IMG_W;
        float xi = xf + t + cx;
        #pragma unroll
        for (int i = 0; i < 4; i++)
            r[i] = bilin_h(img, xi, y + i);
    } else if (op == 4) {                       // trans_y
        float t = -s * 0.15f * (float)IMG_H;
        float yi[4];
        #pragma unroll
        for (int i = 0; i < 4; i++) yi[i] = yf[i] + t + cy;
        bilin_v4(img, yi, x, r);
    } else {                                    // sharpness
        float f = (s > 0.f) ? 1.45f : (1.0f / 1.45f);
        sharp4(img, f, x, y, r);
    }
}

// ---------------------------------------------------------------------------
// reduce0: per-image partial sums of original (only op0 == contrast)
// ---------------------------------------------------------------------------
__global__ void reduce0_kernel(const float* __restrict__ in,
                               const int* __restrict__ op_ids)
{
    int b = blockIdx.y;
    if (op_ids[b * 2] != 6) return;
    const float4* img = (const float4*)(in + (size_t)b * NPEL);
    float s = 0.f;
    for (int i = blockIdx.x * 256 + threadIdx.x; i < NPEL / 4; i += RBLK * 256) {
        float4 v = img[i];
        s += v.x + v.y + v.z + v.w;
    }
    __shared__ float sd[256];
    sd[threadIdx.x] = s;
    __syncthreads();
    #pragma unroll
    for (int st = 128; st > 0; st >>= 1) {
        if (threadIdx.x < st) sd[threadIdx.x] += sd[threadIdx.x + st];
        __syncthreads();
    }
    if (threadIdx.x == 0) g_partial0[b * RBLK + blockIdx.x] = sd[0];
}

// ---------------------------------------------------------------------------
// reduce1: partial sums of the materialized intermediate (op1 == contrast)
// ---------------------------------------------------------------------------
__global__ void reduce1_kernel(const int* __restrict__ op_ids)
{
    int b = blockIdx.y;
    if (op_ids[b * 2 + 1] != 6) return;
    const float4* img = (const float4*)(g_scratch + (size_t)b * NPEL);
    float s = 0.f;
    for (int i = blockIdx.x * 256 + threadIdx.x; i < NPEL / 4; i += RBLK * 256) {
        float4 v = img[i];
        s += v.x + v.y + v.z + v.w;
    }
    __shared__ float sd[256];
    sd[threadIdx.x] = s;
    __syncthreads();
    #pragma unroll
    for (int st = 128; st > 0; st >>= 1) {
        if (threadIdx.x < st) sd[threadIdx.x] += sd[threadIdx.x + st];
        __syncthreads();
    }
    if (threadIdx.x == 0) g_partial1[b * RBLK + blockIdx.x] = sd[0];
}

// ---------------------------------------------------------------------------
// pass1: layer 0. op1==brightness fused inline -> out, else -> scratch.
// Pointwise op0: float4 streaming. Gather op0: quad-row (NPIX/4 threads).
// ---------------------------------------------------------------------------
__global__ void pass1_kernel(const float* __restrict__ in,
                             float* __restrict__ out,
                             const int* __restrict__ op_ids,
                             const int* __restrict__ signs)
{
    const int b   = blockIdx.z;
    const int idx = blockIdx.x * blockDim.x + threadIdx.x;

    const int op0 = op_ids[b * 2], op1 = op_ids[b * 2 + 1];
    const float s0 = signs[b * 2]     ? 1.f : -1.f;
    const float s1 = signs[b * 2 + 1] ? 1.f : -1.f;
    const bool  fuse_b = (op1 == 5);
    const float f1 = (s1 > 0.f) ? 1.45f : (1.0f / 1.45f);

    const float* img = in + (size_t)b * NPEL;
    float* dstbase = (fuse_b ? out : g_scratch) + (size_t)b * NPEL;

    if (op0 == 5 || op0 == 6) {                 // pointwise: float4 streaming
        if (idx >= NPEL / 4) return;
        const float f0 = (s0 > 0.f) ? 1.45f : (1.0f / 1.45f);
        float4 v = ((const float4*)img)[idx];
        float t[4] = { v.x, v.y, v.z, v.w };
        if (op0 == 5) {
            #pragma unroll
            for (int k = 0; k < 4; k++)
                t[k] = fminf(fmaxf(f0 * t[k], 0.f), 1.f);
        } else {
            const float m = inline_mean(g_partial0, b);
            #pragma unroll
            for (int k = 0; k < 4; k++)
                t[k] = fminf(fmaxf(m + f0 * (t[k] - m), 0.f), 1.f);
        }
        if (fuse_b) {
            #pragma unroll
            for (int k = 0; k < 4; k++)
                t[k] = fminf(fmaxf(f1 * t[k], 0.f), 1.f);
        }
        ((float4*)dstbase)[idx] = make_float4(t[0], t[1], t[2], t[3]);
        return;
    }

    // gather path: quad-row, first quarter of the threads active
    if (idx >= NPIX / 4) return;
    const int y = (idx >> 9) * 4;
    const int x = idx & (IMG_W - 1);

    F3 r[4];
    apply_gather4(img, op0, s0, x, y, r);

    if (fuse_b) {
        #pragma unroll
        for (int i = 0; i < 4; i++) {
            r[i].x = fminf(fmaxf(f1 * r[i].x, 0.f), 1.f);
            r[i].y = fminf(fmaxf(f1 * r[i].y, 0.f), 1.f);
            r[i].z = fminf(fmaxf(f1 * r[i].z, 0.f), 1.f);
        }
    }

    float* o = dstbase + ((size_t)y * IMG_W + x) * 3;
    #pragma unroll
    for (int i = 0; i < 4; i++) {
        o[0] = r[i].x; o[1] = r[i].y; o[2] = r[i].z;
        o += ROWF;
    }
}

// ---------------------------------------------------------------------------
// pass2: layer 1 from scratch -> out (op1==brightness already done)
// ---------------------------------------------------------------------------
__global__ void pass2_kernel(float* __restrict__ out,
                             const int* __restrict__ op_ids,
                             const int* __restrict__ signs)
{
    const int b   = blockIdx.z;
    const int op1 = op_ids[b * 2 + 1];
    if (op1 == 5) return;

    const int idx = blockIdx.x * blockDim.x + threadIdx.x;
    const float s1 = signs[b * 2 + 1] ? 1.f : -1.f;
    const float f1 = (s1 > 0.f) ? 1.45f : (1.0f / 1.45f);

    const float* img = g_scratch + (size_t)b * NPEL;
    float* outb = out + (size_t)b * NPEL;

    if (op1 == 6) {                             // contrast: float4 streaming
        if (idx >= NPEL / 4) return;
        const float m = inline_mean(g_partial1, b);
        float4 v = ((const float4*)img)[idx];
        float t[4] = { v.x, v.y, v.z, v.w };
        #pragma unroll
        for (int k = 0; k < 4; k++)
            t[k] = fminf(fmaxf(m + f1 * (t[k] - m), 0.f), 1.f);
        ((float4*)outb)[idx] = make_float4(t[0], t[1], t[2], t[3]);
        return;
    }

    // gather path: quad-row
    if (idx >= NPIX / 4) return;
    const int y = (idx >> 9) * 4;
    const int x = idx & (IMG_W - 1);

    F3 r[4];
    apply_gather4(img, op1, s1, x, y, r);

    float* o = outb + ((size_t)y * IMG_W + x) * 3;
    #pragma unroll
    for (int i = 0; i < 4; i++) {
        o[0] = r[i].x; o[1] = r[i].y; o[2] = r[i].z;
        o += ROWF;
    }
}

// ---------------------------------------------------------------------------
extern "C" void kernel_launch(void* const* d_in, const int* in_sizes, int n_in,
                              void* d_out, int out_size)
{
    const float* images = (const float*)d_in[0];
    const int*   op_ids = (const int*)  d_in[1];
    const int*   signs  = (const int*)  d_in[2];
    float*       out    = (float*)d_out;

    dim3 rgrid(RBLK, NB);
    dim3 agrid(NPIX / 256, 1, NB);

    reduce0_kernel<<<rgrid, 256>>>(images, op_ids);
    pass1_kernel  <<<agrid, 256>>>(images, out, op_ids, signs);
    reduce1_kernel<<<rgrid, 256>>>(op_ids);
    pass2_kernel  <<<agrid, 256>>>(out, op_ids, signs);
}

// round 11
// speedup vs baseline: 1.0424x; 1.0424x over previous
#include <cuda_runtime.h>
#include <math.h>

#define IMG_H 512
#define IMG_W 512
#define NB    64
#define NPIX  (IMG_H * IMG_W)
#define NPEL  (NPIX * 3)
#define RBLK  32
#define ROWF  (IMG_W * 3)

__device__ float g_scratch[(size_t)NB * NPEL];
__device__ float g_partial0[NB * RBLK];
__device__ float g_partial1[NB * RBLK];

struct F3 { float x, y, z; };

__device__ __forceinline__ float inline_mean(const float* __restrict__ part, int b)
{
    float s = 0.f;
    #pragma unroll
    for (int i = 0; i < RBLK; i++) s += part[b * RBLK + i];
    return s * (1.0f / (float)NPEL);
}

// ---------------------------------------------------------------------------
// horizontal 2-tap bilinear (wy == 0 exactly)
// ---------------------------------------------------------------------------
__device__ __forceinline__ F3 bilin_h(const float* __restrict__ img, float xi, int y)
{
    float x0f = floorf(xi);
    float wx  = xi - x0f;
    float w0  = 1.f - wx;
    int   x0  = (int)x0f;
    const float* row = img + (size_t)y * ROWF;
    F3 r;
    if (x0 >= 0 && x0 < IMG_W - 1) {
        const float* p = row + x0 * 3;
        r.x = w0 * p[0] + wx * p[3];
        r.y = w0 * p[1] + wx * p[4];
        r.z = w0 * p[2] + wx * p[5];
    } else {
        bool v0 = (x0 >= 0)  && (x0 <= IMG_W - 1);
        bool v1 = (x0 >= -1) && (x0 <= IMG_W - 2);
        int xc0 = min(max(x0,     0), IMG_W - 1);
        int xc1 = min(max(x0 + 1, 0), IMG_W - 1);
        const float* p0 = row + xc0 * 3;
        const float* p1 = row + xc1 * 3;
        float a0 = v0 ? p0[0] : 0.5f, a1 = v0 ? p0[1] : 0.5f, a2 = v0 ? p0[2] : 0.5f;
        float b0 = v1 ? p1[0] : 0.5f, b1 = v1 ? p1[1] : 0.5f, b2 = v1 ? p1[2] : 0.5f;
        r.x = w0 * a0 + wx * b0;
        r.y = w0 * a1 + wx * b1;
        r.z = w0 * a2 + wx * b2;
    }
    return r;
}

// ---------------------------------------------------------------------------
// vertical 2-tap bilinear, single output (border/fallback)
// ---------------------------------------------------------------------------
__device__ __forceinline__ F3 bilin_v(const float* __restrict__ img, float yi, int x)
{
    float y0f = floorf(yi);
    float wy  = yi - y0f;
    float w0  = 1.f - wy;
    int   y0  = (int)y0f;
    F3 r;
    if (y0 >= 0 && y0 < IMG_H - 1) {
        const float* p = img + ((size_t)y0 * IMG_W + x) * 3;
        const float* q = p + ROWF;
        r.x = w0 * p[0] + wy * q[0];
        r.y = w0 * p[1] + wy * q[1];
        r.z = w0 * p[2] + wy * q[2];
    } else {
        bool v0 = (y0 >= 0)  && (y0 <= IMG_H - 1);
        bool v1 = (y0 >= -1) && (y0 <= IMG_H - 2);
        int yc0 = min(max(y0,     0), IMG_H - 1);
        int yc1 = min(max(y0 + 1, 0), IMG_H - 1);
        const float* p0 = img + ((size_t)yc0 * IMG_W + x) * 3;
        const float* p1 = img + ((size_t)yc1 * IMG_W + x) * 3;
        float a0 = v0 ? p0[0] : 0.5f, a1 = v0 ? p0[1] : 0.5f, a2 = v0 ? p0[2] : 0.5f;
        float b0 = v1 ? p1[0] : 0.5f, b1 = v1 ? p1[1] : 0.5f, b2 = v1 ? p1[2] : 0.5f;
        r.x = w0 * a0 + wy * b0;
        r.y = w0 * a1 + wy * b1;
        r.z = w0 * a2 + wy * b2;
    }
    return r;
}

// ---------------------------------------------------------------------------
// dual-row vertical bilinear (pass1): shares middle tap row
// ---------------------------------------------------------------------------
__device__ __forceinline__ void bilin_v2(const float* __restrict__ img,
                                         float yi0, float yi1, int x,
                                         F3& r0, F3& r1)
{
    float k0f = floorf(yi0), k1f = floorf(yi1);
    int   k0  = (int)k0f,    k1  = (int)k1f;
    float wy0 = yi0 - k0f,   wy1 = yi1 - k1f;
    if (k1 == k0 + 1 && k0 >= 0 && k0 + 2 <= IMG_H - 1) {
        const float* p = img + ((size_t)k0 * IMG_W + x) * 3;
        const float* q = p + ROWF;
        const float* t = q + ROWF;
        float a0 = p[0], a1 = p[1], a2 = p[2];
        float b0 = q[0], b1 = q[1], b2 = q[2];
        float c0 = t[0], c1 = t[1], c2 = t[2];
        float u0 = 1.f - wy0, u1 = 1.f - wy1;
        r0.x = u0 * a0 + wy0 * b0;
        r0.y = u0 * a1 + wy0 * b1;
        r0.z = u0 * a2 + wy0 * b2;
        r1.x = u1 * b0 + wy1 * c0;
        r1.y = u1 * b1 + wy1 * c1;
        r1.z = u1 * b2 + wy1 * c2;
    } else {
        r0 = bilin_v(img, yi0, x);
        r1 = bilin_v(img, yi1, x);
    }
}

// ---------------------------------------------------------------------------
// quad-row vertical bilinear (pass2): 5 tap rows for 4 outputs when aligned
// ---------------------------------------------------------------------------
__device__ __forceinline__ void bilin_v4(const float* __restrict__ img,
                                         const float yi[4], int x, F3 r[4])
{
    float k0f = floorf(yi[0]);
    int   k0  = (int)k0f;
    bool aligned = (k0 >= 0) && (k0 + 4 <= IMG_H - 1);
    #pragma unroll
    for (int i = 1; i < 4; i++)
        aligned = aligned && ((int)floorf(yi[i]) == k0 + i);
    if (aligned) {
        const float* p = img + ((size_t)k0 * IMG_W + x) * 3;
        float rv[5][3];
        #pragma unroll
        for (int j = 0; j < 5; j++) {
            rv[j][0] = p[0]; rv[j][1] = p[1]; rv[j][2] = p[2];
            p += ROWF;
        }
        #pragma unroll
        for (int i = 0; i < 4; i++) {
            float wy = yi[i] - floorf(yi[i]);
            float w0 = 1.f - wy;
            r[i].x = w0 * rv[i][0] + wy * rv[i+1][0];
            r[i].y = w0 * rv[i][1] + wy * rv[i+1][1];
            r[i].z = w0 * rv[i][2] + wy * rv[i+1][2];
        }
    } else {
        #pragma unroll
        for (int i = 0; i < 4; i++) r[i] = bilin_v(img, yi[i], x);
    }
}

// ---------------------------------------------------------------------------
// general 4-tap bilinear (rotate)
// ---------------------------------------------------------------------------
__device__ __forceinline__ F3 bilin4(const float* __restrict__ img, float xi, float yi)
{
    float x0f = floorf(xi), y0f = floorf(yi);
    float wx = xi - x0f,    wy = yi - y0f;
    int   x0 = (int)x0f,    y0 = (int)y0f;
    float w00 = (1.f - wx) * (1.f - wy);
    float w10 = wx * (1.f - wy);
    float w01 = (1.f - wx) * wy;
    float w11 = wx * wy;
    F3 r;
    if (x0 >= 0 && x0 < IMG_W - 1 && y0 >= 0 && y0 < IMG_H - 1) {
        const float* p = img + ((size_t)y0 * IMG_W + x0) * 3;
        const float* q = p + ROWF;
        r.x = w00 * p[0] + w10 * p[3] + w01 * q[0] + w11 * q[3];
        r.y = w00 * p[1] + w10 * p[4] + w01 * q[1] + w11 * q[4];
        r.z = w00 * p[2] + w10 * p[5] + w01 * q[2] + w11 * q[5];
    } else {
        bool vx0 = (x0 >= 0)  && (x0 <= IMG_W - 1);
        bool vx1 = (x0 >= -1) && (x0 <= IMG_W - 2);
        bool vy0 = (y0 >= 0)  && (y0 <= IMG_H - 1);
        bool vy1 = (y0 >= -1) && (y0 <= IMG_H - 2);
        int xc0 = min(max(x0,     0), IMG_W - 1);
        int xc1 = min(max(x0 + 1, 0), IMG_W - 1);
        int yc0 = min(max(y0,     0), IMG_H - 1);
        int yc1 = min(max(y0 + 1, 0), IMG_H - 1);
        const float* p00 = img + ((size_t)yc0 * IMG_W + xc0) * 3;
        const float* p10 = img + ((size_t)yc0 * IMG_W + xc1) * 3;
        const float* p01 = img + ((size_t)yc1 * IMG_W + xc0) * 3;
        const float* p11 = img + ((size_t)yc1 * IMG_W + xc1) * 3;
        bool v00 = vx0 && vy0, v10 = vx1 && vy0, v01 = vx0 && vy1, v11 = vx1 && vy1;
        r.x = w00 * (v00 ? p00[0] : 0.5f) + w10 * (v10 ? p10[0] : 0.5f)
            + w01 * (v01 ? p01[0] : 0.5f) + w11 * (v11 ? p11[0] : 0.5f);
        r.y = w00 * (v00 ? p00[1] : 0.5f) + w10 * (v10 ? p10[1] : 0.5f)
            + w01 * (v01 ? p01[1] : 0.5f) + w11 * (v11 ? p11[1] : 0.5f);
        r.z = w00 * (v00 ? p00[2] : 0.5f) + w10 * (v10 ? p10[2] : 0.5f)
            + w01 * (v01 ? p01[2] : 0.5f) + w11 * (v11 ? p11[2] : 0.5f);
    }
    return r;
}

// ---------------------------------------------------------------------------
// single-pixel sharpness (border/fallback)
// ---------------------------------------------------------------------------
__device__ __forceinline__ F3 sharp3x3(const float* __restrict__ img,
                                       float f, int x, int y)
{
    const float* p = img + ((size_t)y * IMG_W + x) * 3;
    float v0 = p[0], v1 = p[1], v2 = p[2];
    float s0 = 0.f, s1 = 0.f, s2 = 0.f;
    #pragma unroll
    for (int dy = -1; dy <= 1; dy++) {
        int yy = min(max(y + dy, 0), IMG_H - 1);
        #pragma unroll
        for (int dx = -1; dx <= 1; dx++) {
            int xx = min(max(x + dx, 0), IMG_W - 1);
            float k = (dx == 0 && dy == 0) ? (5.0f/13.0f) : (1.0f/13.0f);
            const float* q = img + ((size_t)yy * IMG_W + xx) * 3;
            s0 += k * q[0]; s1 += k * q[1]; s2 += k * q[2];
        }
    }
    F3 r;
    r.x = fminf(fmaxf(s0 + f * (v0 - s0), 0.f), 1.f);
    r.y = fminf(fmaxf(s1 + f * (v1 - s1), 0.f), 1.f);
    r.z = fminf(fmaxf(s2 + f * (v2 - s2), 0.f), 1.f);
    return r;
}

// ---------------------------------------------------------------------------
// dual-row sharpness (pass1)
// ---------------------------------------------------------------------------
__device__ __forceinline__ void sharp2(const float* __restrict__ img,
                                       float f, int x, int y,
                                       F3& r0, F3& r1)
{
    if (x >= 1 && x <= IMG_W - 2 && y >= 1 && y + 2 <= IMG_H - 1) {
        const float* pm = img + ((size_t)(y - 1) * IMG_W + x) * 3;
        const float* pc = pm + ROWF;
        const float* pd = pc + ROWF;
        const float* pp = pd + ROWF;
        float Rm0 = pm[-3] + pm[0] + pm[3];
        float Rm1 = pm[-2] + pm[1] + pm[4];
        float Rm2 = pm[-1] + pm[2] + pm[5];
        float v00 = pc[0], v01 = pc[1], v02 = pc[2];
        float Rc0 = pc[-3] + v00 + pc[3];
        float Rc1 = pc[-2] + v01 + pc[4];
        float Rc2 = pc[-1] + v02 + pc[5];
        float v10 = pd[0], v11 = pd[1], v12 = pd[2];
        float Rd0 = pd[-3] + v10 + pd[3];
        float Rd1 = pd[-2] + v11 + pd[4];
        float Rd2 = pd[-1] + v12 + pd[5];
        float Rp0 = pp[-3] + pp[0] + pp[3];
        float Rp1 = pp[-2] + pp[1] + pp[4];
        float Rp2 = pp[-1] + pp[2] + pp[5];
        float s00 = (Rm0 + Rc0 + Rd0 + 4.f * v00) * (1.f / 13.f);
        float s01 = (Rm1 + Rc1 + Rd1 + 4.f * v01) * (1.f / 13.f);
        float s02 = (Rm2 + Rc2 + Rd2 + 4.f * v02) * (1.f / 13.f);
        float s10 = (Rc0 + Rd0 + Rp0 + 4.f * v10) * (1.f / 13.f);
        float s11 = (Rc1 + Rd1 + Rp1 + 4.f * v11) * (1.f / 13.f);
        float s12 = (Rc2 + Rd2 + Rp2 + 4.f * v12) * (1.f / 13.f);
        r0.x = fminf(fmaxf(s00 + f * (v00 - s00), 0.f), 1.f);
        r0.y = fminf(fmaxf(s01 + f * (v01 - s01), 0.f), 1.f);
        r0.z = fminf(fmaxf(s02 + f * (v02 - s02), 0.f), 1.f);
        r1.x = fminf(fmaxf(s10 + f * (v10 - s10), 0.f), 1.f);
        r1.y = fminf(fmaxf(s11 + f * (v11 - s11), 0.f), 1.f);
        r1.z = fminf(fmaxf(s12 + f * (v12 - s12), 0.f), 1.f);
    } else {
        r0 = sharp3x3(img, f, x, y);
        r1 = sharp3x3(img, f, x, y + 1);
    }
}

// ---------------------------------------------------------------------------
// quad-row sharpness (pass2)
// ---------------------------------------------------------------------------
__device__ __forceinline__ void sharp4(const float* __restrict__ img,
                                       float f, int x, int y, F3 r[4])
{
    if (x >= 1 && x <= IMG_W - 2 && y >= 1 && y + 4 <= IMG_H - 1) {
        const float* base = img + ((size_t)(y - 1) * IMG_W + x) * 3;
        float out[4][3];
        #pragma unroll
        for (int ch = 0; ch < 3; ch++) {
            float R[6], V[6];
            #pragma unroll
            for (int j = 0; j < 6; j++) {
                const float* p = base + (size_t)j * ROWF;
                float l = p[ch - 3], c = p[ch], rr = p[ch + 3];
                V[j] = c;
                R[j] = l + c + rr;
            }
            #pragma unroll
            for (int i = 0; i < 4; i++) {
                float v = V[i + 1];
                float s = (R[i] + R[i+1] + R[i+2] + 4.f * v) * (1.f / 13.f);
                out[i][ch] = fminf(fmaxf(s + f * (v - s), 0.f), 1.f);
            }
        }
        #pragma unroll
        for (int i = 0; i < 4; i++) {
            r[i].x = out[i][0]; r[i].y = out[i][1]; r[i].z = out[i][2];
        }
    } else {
        #pragma unroll
        for (int i = 0; i < 4; i++) r[i] = sharp3x3(img, f, x, y + i);
    }
}

// ---------------------------------------------------------------------------
// dual-row gather dispatch (pass1)
// ---------------------------------------------------------------------------
__device__ __forceinline__ void apply_gather2(const float* __restrict__ img,
                                              int op, float s, int x, int y,
                                              F3& r0, F3& r1)
{
    const float cx = (IMG_W - 1) * 0.5f, cy = (IMG_H - 1) * 0.5f;
    const float xf  = (float)x - cx;
    const float yf0 = (float)y - cy;
    const float yf1 = (float)(y + 1) - cy;
    if (op == 0) {
        float th = s * 0.2617993877991494f;
        float co = cosf(th), si = sinf(th);
        r0 = bilin4(img, co * xf + si * yf0 + cx, -si * xf + co * yf0 + cy);
        r1 = bilin4(img, co * xf + si * yf1 + cx, -si * xf + co * yf1 + cy);
    } else if (op == 1) {
        float sh = -s * 0.15f;
        r0 = bilin_h(img, xf + sh * yf0 + cx, y);
        r1 = bilin_h(img, xf + sh * yf1 + cx, y + 1);
    } else if (op == 2) {
        float sh = -s * 0.15f;
        bilin_v2(img, yf0 + sh * xf + cy, yf1 + sh * xf + cy, x, r0, r1);
    } else if (op == 3) {
        float t = -s * 0.15f * (float)IMG_W;
        float xi = xf + t + cx;
        r0 = bilin_h(img, xi, y);
        r1 = bilin_h(img, xi, y + 1);
    } else if (op == 4) {
        float t = -s * 0.15f * (float)IMG_H;
        bilin_v2(img, yf0 + t + cy, yf1 + t + cy, x, r0, r1);
    } else {
        float f = (s > 0.f) ? 1.45f : (1.0f / 1.45f);
        sharp2(img, f, x, y, r0, r1);
    }
}

// ---------------------------------------------------------------------------
// quad-row gather dispatch (pass2)
// ---------------------------------------------------------------------------
__device__ __forceinline__ void apply_gather4(const float* __restrict__ img,
                                              int op, float s, int x, int y,
                                              F3 r[4])
{
    const float cx = (IMG_W - 1) * 0.5f, cy = (IMG_H - 1) * 0.5f;
    const float xf = (float)x - cx;
    float yf[4];
    #pragma unroll
    for (int i = 0; i < 4; i++) yf[i] = (float)(y + i) - cy;

    if (op == 0) {
        float th = s * 0.2617993877991494f;
        float co = cosf(th), si = sinf(th);
        #pragma unroll
        for (int i = 0; i < 4; i++)
            r[i] = bilin4(img, co * xf + si * yf[i] + cx,
                               -si * xf + co * yf[i] + cy);
    } else if (op == 1) {
        float sh = -s * 0.15f;
        #pragma unroll
        for (int i = 0; i < 4; i++)
            r[i] = bilin_h(img, xf + sh * yf[i] + cx, y + i);
    } else if (op == 2) {
        float sh = -s * 0.15f;
        float yi[4];
        #pragma unroll
        for (int i = 0; i < 4; i++) yi[i] = yf[i] + sh * xf + cy;
        bilin_v4(img, yi, x, r);
    } else if (op == 3) {
        float t = -s * 0.15f * (float)IMG_W;
        float xi = xf + t + cx;
        #pragma unroll
        for (int i = 0; i < 4; i++)
            r[i] = bilin_h(img, xi, y + i);
    } else if (op == 4) {
        float t = -s * 0.15f * (float)IMG_H;
        float yi[4];
        #pragma unroll
        for (int i = 0; i < 4; i++) yi[i] = yf[i] + t + cy;
        bilin_v4(img, yi, x, r);
    } else {
        float f = (s > 0.f) ? 1.45f : (1.0f / 1.45f);
        sharp4(img, f, x, y, r);
    }
}

// ---------------------------------------------------------------------------
// reduce0: per-image partial sums of original (only op0 == contrast)
// ---------------------------------------------------------------------------
__global__ void reduce0_kernel(const float* __restrict__ in,
                               const int* __restrict__ op_ids)
{
    int b = blockIdx.y;
    if (op_ids[b * 2] != 6) return;
    const float4* img = (const float4*)(in + (size_t)b * NPEL);
    float s = 0.f;
    for (int i = blockIdx.x * 256 + threadIdx.x; i < NPEL / 4; i += RBLK * 256) {
        float4 v = img[i];
        s += v.x + v.y + v.z + v.w;
    }
    __shared__ float sd[256];
    sd[threadIdx.x] = s;
    __syncthreads();
    #pragma unroll
    for (int st = 128; st > 0; st >>= 1) {
        if (threadIdx.x < st) sd[threadIdx.x] += sd[threadIdx.x + st];
        __syncthreads();
    }
    if (threadIdx.x == 0) g_partial0[b * RBLK + blockIdx.x] = sd[0];
}

// ---------------------------------------------------------------------------
// reduce1: partial sums of the materialized intermediate (op1 == contrast)
// ---------------------------------------------------------------------------
__global__ void reduce1_kernel(const int* __restrict__ op_ids)
{
    int b = blockIdx.y;
    if (op_ids[b * 2 + 1] != 6) return;
    const float4* img = (const float4*)(g_scratch + (size_t)b * NPEL);
    float s = 0.f;
    for (int i = blockIdx.x * 256 + threadIdx.x; i < NPEL / 4; i += RBLK * 256) {
        float4 v = img[i];
        s += v.x + v.y + v.z + v.w;
    }
    __shared__ float sd[256];
    sd[threadIdx.x] = s;
    __syncthreads();
    #pragma unroll
    for (int st = 128; st > 0; st >>= 1) {
        if (threadIdx.x < st) sd[threadIdx.x] += sd[threadIdx.x + st];
        __syncthreads();
    }
    if (threadIdx.x == 0) g_partial1[b * RBLK + blockIdx.x] = sd[0];
}

// ---------------------------------------------------------------------------
// pass1: layer 0. op1==brightness fused inline -> out, else -> scratch.
// Pointwise op0: float4 streaming. Gather op0: DUAL-row (measured best).
// ---------------------------------------------------------------------------
__global__ void pass1_kernel(const float* __restrict__ in,
                             float* __restrict__ out,
                             const int* __restrict__ op_ids,
                             const int* __restrict__ signs)
{
    const int b   = blockIdx.z;
    const int idx = blockIdx.x * blockDim.x + threadIdx.x;

    const int op0 = op_ids[b * 2], op1 = op_ids[b * 2 + 1];
    const float s0 = signs[b * 2]     ? 1.f : -1.f;
    const float s1 = signs[b * 2 + 1] ? 1.f : -1.f;
    const bool  fuse_b = (op1 == 5);
    const float f1 = (s1 > 0.f) ? 1.45f : (1.0f / 1.45f);

    const float* img = in + (size_t)b * NPEL;
    float* dstbase = (fuse_b ? out : g_scratch) + (size_t)b * NPEL;

    if (op0 == 5 || op0 == 6) {
        if (idx >= NPEL / 4) return;
        const float f0 = (s0 > 0.f) ? 1.45f : (1.0f / 1.45f);
        float4 v = ((const float4*)img)[idx];
        float t[4] = { v.x, v.y, v.z, v.w };
        if (op0 == 5) {
            #pragma unroll
            for (int k = 0; k < 4; k++)
                t[k] = fminf(fmaxf(f0 * t[k], 0.f), 1.f);
        } else {
            const float m = inline_mean(g_partial0, b);
            #pragma unroll
            for (int k = 0; k < 4; k++)
                t[k] = fminf(fmaxf(m + f0 * (t[k] - m), 0.f), 1.f);
        }
        if (fuse_b) {
            #pragma unroll
            for (int k = 0; k < 4; k++)
                t[k] = fminf(fmaxf(f1 * t[k], 0.f), 1.f);
        }
        ((float4*)dstbase)[idx] = make_float4(t[0], t[1], t[2], t[3]);
        return;
    }

    // gather path: dual-row
    if (idx >= NPIX / 2) return;
    const int y = (idx >> 9) * 2;
    const int x = idx & (IMG_W - 1);

    F3 r0, r1;
    apply_gather2(img, op0, s0, x, y, r0, r1);

    if (fuse_b) {
        r0.x = fminf(fmaxf(f1 * r0.x, 0.f), 1.f);
        r0.y = fminf(fmaxf(f1 * r0.y, 0.f), 1.f);
        r0.z = fminf(fmaxf(f1 * r0.z, 0.f), 1.f);
        r1.x = fminf(fmaxf(f1 * r1.x, 0.f), 1.f);
        r1.y = fminf(fmaxf(f1 * r1.y, 0.f), 1.f);
        r1.z = fminf(fmaxf(f1 * r1.z, 0.f), 1.f);
    }

    float* o0 = dstbase + ((size_t)y * IMG_W + x) * 3;
    float* o1 = o0 + ROWF;
    o0[0] = r0.x; o0[1] = r0.y; o0[2] = r0.z;
    o1[0] = r1.x; o1[1] = r1.y; o1[2] = r1.z;
}

// ---------------------------------------------------------------------------
// pass2: layer 1 from scratch -> out. Gather: QUAD-row (measured best).
// ---------------------------------------------------------------------------
__global__ void pass2_kernel(float* __restrict__ out,
                             const int* __restrict__ op_ids,
                             const int* __restrict__ signs)
{
    const int b   = blockIdx.z;
    const int op1 = op_ids[b * 2 + 1];
    if (op1 == 5) return;

    const int idx = blockIdx.x * blockDim.x + threadIdx.x;
    const float s1 = signs[b * 2 + 1] ? 1.f : -1.f;
    const float f1 = (s1 > 0.f) ? 1.45f : (1.0f / 1.45f);

    const float* img = g_scratch + (size_t)b * NPEL;
    float* outb = out + (size_t)b * NPEL;

    if (op1 == 6) {
        if (idx >= NPEL / 4) return;
        const float m = inline_mean(g_partial1, b);
        float4 v = ((const float4*)img)[idx];
        float t[4] = { v.x, v.y, v.z, v.w };
        #pragma unroll
        for (int k = 0; k < 4; k++)
            t[k] = fminf(fmaxf(m + f1 * (t[k] - m), 0.f), 1.f);
        ((float4*)outb)[idx] = make_float4(t[0], t[1], t[2], t[3]);
        return;
    }

    // gather path: quad-row
    if (idx >= NPIX / 4) return;
    const int y = (idx >> 9) * 4;
    const int x = idx & (IMG_W - 1);

    F3 r[4];
    apply_gather4(img, op1, s1, x, y, r);

    float* o = outb + ((size_t)y * IMG_W + x) * 3;
    #pragma unroll
    for (int i = 0; i < 4; i++) {
        o[0] = r[i].x; o[1] = r[i].y; o[2] = r[i].z;
        o += ROWF;
    }
}

// ---------------------------------------------------------------------------
extern "C" void kernel_launch(void* const* d_in, const int* in_sizes, int n_in,
                              void* d_out, int out_size)
{
    const float* images = (const float*)d_in[0];
    const int*   op_ids = (const int*)  d_in[1];
    const int*   signs  = (const int*)  d_in[2];
    float*       out    = (float*)d_out;

    dim3 rgrid(RBLK, NB);
    dim3 agrid(NPIX / 256, 1, NB);

    reduce0_kernel<<<rgrid, 256>>>(images, op_ids);
    pass1_kernel  <<<agrid, 256>>>(images, out, op_ids, signs);
    reduce1_kernel<<<rgrid, 256>>>(op_ids);
    pass2_kernel  <<<agrid, 256>>>(out, op_ids, signs);
}

// round 12
// speedup vs baseline: 1.1330x; 1.0869x over previous
#include <cuda_runtime.h>
#include <math.h>

#define IMG_H 512
#define IMG_W 512
#define NB    64
#define NPIX  (IMG_H * IMG_W)
#define NPEL  (NPIX * 3)
#define RBLK  32
#define ROWF  (IMG_W * 3)
#define P1BLK 512          // pass1 blocks per image (= NPIX/2/256)

__device__ float g_scratch[(size_t)NB * NPEL];
__device__ float g_partial0[NB * RBLK];
__device__ float g_partial1[NB * P1BLK];
__device__ float g_mean1[NB];

struct F3 { float x, y, z; };

__device__ __forceinline__ float inline_mean(const float* __restrict__ part, int b)
{
    float s = 0.f;
    #pragma unroll
    for (int i = 0; i < RBLK; i++) s += part[b * RBLK + i];
    return s * (1.0f / (float)NPEL);
}

// ---------------------------------------------------------------------------
// horizontal 2-tap bilinear (wy == 0 exactly)
// ---------------------------------------------------------------------------
__device__ __forceinline__ F3 bilin_h(const float* __restrict__ img, float xi, int y)
{
    float x0f = floorf(xi);
    float wx  = xi - x0f;
    float w0  = 1.f - wx;
    int   x0  = (int)x0f;
    const float* row = img + (size_t)y * ROWF;
    F3 r;
    if (x0 >= 0 && x0 < IMG_W - 1) {
        const float* p = row + x0 * 3;
        r.x = w0 * p[0] + wx * p[3];
        r.y = w0 * p[1] + wx * p[4];
        r.z = w0 * p[2] + wx * p[5];
    } else {
        bool v0 = (x0 >= 0)  && (x0 <= IMG_W - 1);
        bool v1 = (x0 >= -1) && (x0 <= IMG_W - 2);
        int xc0 = min(max(x0,     0), IMG_W - 1);
        int xc1 = min(max(x0 + 1, 0), IMG_W - 1);
        const float* p0 = row + xc0 * 3;
        const float* p1 = row + xc1 * 3;
        float a0 = v0 ? p0[0] : 0.5f, a1 = v0 ? p0[1] : 0.5f, a2 = v0 ? p0[2] : 0.5f;
        float b0 = v1 ? p1[0] : 0.5f, b1 = v1 ? p1[1] : 0.5f, b2 = v1 ? p1[2] : 0.5f;
        r.x = w0 * a0 + wx * b0;
        r.y = w0 * a1 + wx * b1;
        r.z = w0 * a2 + wx * b2;
    }
    return r;
}

// ---------------------------------------------------------------------------
// vertical 2-tap bilinear, single output (border/fallback)
// ---------------------------------------------------------------------------
__device__ __forceinline__ F3 bilin_v(const float* __restrict__ img, float yi, int x)
{
    float y0f = floorf(yi);
    float wy  = yi - y0f;
    float w0  = 1.f - wy;
    int   y0  = (int)y0f;
    F3 r;
    if (y0 >= 0 && y0 < IMG_H - 1) {
        const float* p = img + ((size_t)y0 * IMG_W + x) * 3;
        const float* q = p + ROWF;
        r.x = w0 * p[0] + wy * q[0];
        r.y = w0 * p[1] + wy * q[1];
        r.z = w0 * p[2] + wy * q[2];
    } else {
        bool v0 = (y0 >= 0)  && (y0 <= IMG_H - 1);
        bool v1 = (y0 >= -1) && (y0 <= IMG_H - 2);
        int yc0 = min(max(y0,     0), IMG_H - 1);
        int yc1 = min(max(y0 + 1, 0), IMG_H - 1);
        const float* p0 = img + ((size_t)yc0 * IMG_W + x) * 3;
        const float* p1 = img + ((size_t)yc1 * IMG_W + x) * 3;
        float a0 = v0 ? p0[0] : 0.5f, a1 = v0 ? p0[1] : 0.5f, a2 = v0 ? p0[2] : 0.5f;
        float b0 = v1 ? p1[0] : 0.5f, b1 = v1 ? p1[1] : 0.5f, b2 = v1 ? p1[2] : 0.5f;
        r.x = w0 * a0 + wy * b0;
        r.y = w0 * a1 + wy * b1;
        r.z = w0 * a2 + wy * b2;
    }
    return r;
}

// ---------------------------------------------------------------------------
// dual-row vertical bilinear (pass1): shares middle tap row
// ---------------------------------------------------------------------------
__device__ __forceinline__ void bilin_v2(const float* __restrict__ img,
                                         float yi0, float yi1, int x,
                                         F3& r0, F3& r1)
{
    float k0f = floorf(yi0), k1f = floorf(yi1);
    int   k0  = (int)k0f,    k1  = (int)k1f;
    float wy0 = yi0 - k0f,   wy1 = yi1 - k1f;
    if (k1 == k0 + 1 && k0 >= 0 && k0 + 2 <= IMG_H - 1) {
        const float* p = img + ((size_t)k0 * IMG_W + x) * 3;
        const float* q = p + ROWF;
        const float* t = q + ROWF;
        float a0 = p[0], a1 = p[1], a2 = p[2];
        float b0 = q[0], b1 = q[1], b2 = q[2];
        float c0 = t[0], c1 = t[1], c2 = t[2];
        float u0 = 1.f - wy0, u1 = 1.f - wy1;
        r0.x = u0 * a0 + wy0 * b0;
        r0.y = u0 * a1 + wy0 * b1;
        r0.z = u0 * a2 + wy0 * b2;
        r1.x = u1 * b0 + wy1 * c0;
        r1.y = u1 * b1 + wy1 * c1;
        r1.z = u1 * b2 + wy1 * c2;
    } else {
        r0 = bilin_v(img, yi0, x);
        r1 = bilin_v(img, yi1, x);
    }
}

// ---------------------------------------------------------------------------
// quad-row vertical bilinear (pass2): 5 tap rows for 4 outputs when aligned
// ---------------------------------------------------------------------------
__device__ __forceinline__ void bilin_v4(const float* __restrict__ img,
                                         const float yi[4], int x, F3 r[4])
{
    float k0f = floorf(yi[0]);
    int   k0  = (int)k0f;
    bool aligned = (k0 >= 0) && (k0 + 4 <= IMG_H - 1);
    #pragma unroll
    for (int i = 1; i < 4; i++)
        aligned = aligned && ((int)floorf(yi[i]) == k0 + i);
    if (aligned) {
        const float* p = img + ((size_t)k0 * IMG_W + x) * 3;
        float rv[5][3];
        #pragma unroll
        for (int j = 0; j < 5; j++) {
            rv[j][0] = p[0]; rv[j][1] = p[1]; rv[j][2] = p[2];
            p += ROWF;
        }
        #pragma unroll
        for (int i = 0; i < 4; i++) {
            float wy = yi[i] - floorf(yi[i]);
            float w0 = 1.f - wy;
            r[i].x = w0 * rv[i][0] + wy * rv[i+1][0];
            r[i].y = w0 * rv[i][1] + wy * rv[i+1][1];
            r[i].z = w0 * rv[i][2] + wy * rv[i+1][2];
        }
    } else {
        #pragma unroll
        for (int i = 0; i < 4; i++) r[i] = bilin_v(img, yi[i], x);
    }
}

// ---------------------------------------------------------------------------
// general 4-tap bilinear (rotate)
// ---------------------------------------------------------------------------
__device__ __forceinline__ F3 bilin4(const float* __restrict__ img, float xi, float yi)
{
    float x0f = floorf(xi), y0f = floorf(yi);
    float wx = xi - x0f,    wy = yi - y0f;
    int   x0 = (int)x0f,    y0 = (int)y0f;
    float w00 = (1.f - wx) * (1.f - wy);
    float w10 = wx * (1.f - wy);
    float w01 = (1.f - wx) * wy;
    float w11 = wx * wy;
    F3 r;
    if (x0 >= 0 && x0 < IMG_W - 1 && y0 >= 0 && y0 < IMG_H - 1) {
        const float* p = img + ((size_t)y0 * IMG_W + x0) * 3;
        const float* q = p + ROWF;
        r.x = w00 * p[0] + w10 * p[3] + w01 * q[0] + w11 * q[3];
        r.y = w00 * p[1] + w10 * p[4] + w01 * q[1] + w11 * q[4];
        r.z = w00 * p[2] + w10 * p[5] + w01 * q[2] + w11 * q[5];
    } else {
        bool vx0 = (x0 >= 0)  && (x0 <= IMG_W - 1);
        bool vx1 = (x0 >= -1) && (x0 <= IMG_W - 2);
        bool vy0 = (y0 >= 0)  && (y0 <= IMG_H - 1);
        bool vy1 = (y0 >= -1) && (y0 <= IMG_H - 2);
        int xc0 = min(max(x0,     0), IMG_W - 1);
        int xc1 = min(max(x0 + 1, 0), IMG_W - 1);
        int yc0 = min(max(y0,     0), IMG_H - 1);
        int yc1 = min(max(y0 + 1, 0), IMG_H - 1);
        const float* p00 = img + ((size_t)yc0 * IMG_W + xc0) * 3;
        const float* p10 = img + ((size_t)yc0 * IMG_W + xc1) * 3;
        const float* p01 = img + ((size_t)yc1 * IMG_W + xc0) * 3;
        const float* p11 = img + ((size_t)yc1 * IMG_W + xc1) * 3;
        bool v00 = vx0 && vy0, v10 = vx1 && vy0, v01 = vx0 && vy1, v11 = vx1 && vy1;
        r.x = w00 * (v00 ? p00[0] : 0.5f) + w10 * (v10 ? p10[0] : 0.5f)
            + w01 * (v01 ? p01[0] : 0.5f) + w11 * (v11 ? p11[0] : 0.5f);
        r.y = w00 * (v00 ? p00[1] : 0.5f) + w10 * (v10 ? p10[1] : 0.5f)
            + w01 * (v01 ? p01[1] : 0.5f) + w11 * (v11 ? p11[1] : 0.5f);
        r.z = w00 * (v00 ? p00[2] : 0.5f) + w10 * (v10 ? p10[2] : 0.5f)
            + w01 * (v01 ? p01[2] : 0.5f) + w11 * (v11 ? p11[2] : 0.5f);
    }
    return r;
}

// ---------------------------------------------------------------------------
// single-pixel sharpness (border/fallback)
// ---------------------------------------------------------------------------
__device__ __forceinline__ F3 sharp3x3(const float* __restrict__ img,
                                       float f, int x, int y)
{
    const float* p = img + ((size_t)y * IMG_W + x) * 3;
    float v0 = p[0], v1 = p[1], v2 = p[2];
    float s0 = 0.f, s1 = 0.f, s2 = 0.f;
    #pragma unroll
    for (int dy = -1; dy <= 1; dy++) {
        int yy = min(max(y + dy, 0), IMG_H - 1);
        #pragma unroll
        for (int dx = -1; dx <= 1; dx++) {
            int xx = min(max(x + dx, 0), IMG_W - 1);
            float k = (dx == 0 && dy == 0) ? (5.0f/13.0f) : (1.0f/13.0f);
            const float* q = img + ((size_t)yy * IMG_W + xx) * 3;
            s0 += k * q[0]; s1 += k * q[1]; s2 += k * q[2];
        }
    }
    F3 r;
    r.x = fminf(fmaxf(s0 + f * (v0 - s0), 0.f), 1.f);
    r.y = fminf(fmaxf(s1 + f * (v1 - s1), 0.f), 1.f);
    r.z = fminf(fmaxf(s2 + f * (v2 - s2), 0.f), 1.f);
    return r;
}

// ---------------------------------------------------------------------------
// dual-row sharpness (pass1)
// ---------------------------------------------------------------------------
__device__ __forceinline__ void sharp2(const float* __restrict__ img,
                                       float f, int x, int y,
                                       F3& r0, F3& r1)
{
    if (x >= 1 && x <= IMG_W - 2 && y >= 1 && y + 2 <= IMG_H - 1) {
        const float* pm = img + ((size_t)(y - 1) * IMG_W + x) * 3;
        const float* pc = pm + ROWF;
        const float* pd = pc + ROWF;
        const float* pp = pd + ROWF;
        float Rm0 = pm[-3] + pm[0] + pm[3];
        float Rm1 = pm[-2] + pm[1] + pm[4];
        float Rm2 = pm[-1] + pm[2] + pm[5];
        float v00 = pc[0], v01 = pc[1], v02 = pc[2];
        float Rc0 = pc[-3] + v00 + pc[3];
        float Rc1 = pc[-2] + v01 + pc[4];
        float Rc2 = pc[-1] + v02 + pc[5];
        float v10 = pd[0], v11 = pd[1], v12 = pd[2];
        float Rd0 = pd[-3] + v10 + pd[3];
        float Rd1 = pd[-2] + v11 + pd[4];
        float Rd2 = pd[-1] + v12 + pd[5];
        float Rp0 = pp[-3] + pp[0] + pp[3];
        float Rp1 = pp[-2] + pp[1] + pp[4];
        float Rp2 = pp[-1] + pp[2] + pp[5];
        float s00 = (Rm0 + Rc0 + Rd0 + 4.f * v00) * (1.f / 13.f);
        float s01 = (Rm1 + Rc1 + Rd1 + 4.f * v01) * (1.f / 13.f);
        float s02 = (Rm2 + Rc2 + Rd2 + 4.f * v02) * (1.f / 13.f);
        float s10 = (Rc0 + Rd0 + Rp0 + 4.f * v10) * (1.f / 13.f);
        float s11 = (Rc1 + Rd1 + Rp1 + 4.f * v11) * (1.f / 13.f);
        float s12 = (Rc2 + Rd2 + Rp2 + 4.f * v12) * (1.f / 13.f);
        r0.x = fminf(fmaxf(s00 + f * (v00 - s00), 0.f), 1.f);
        r0.y = fminf(fmaxf(s01 + f * (v01 - s01), 0.f), 1.f);
        r0.z = fminf(fmaxf(s02 + f * (v02 - s02), 0.f), 1.f);
        r1.x = fminf(fmaxf(s10 + f * (v10 - s10), 0.f), 1.f);
        r1.y = fminf(fmaxf(s11 + f * (v11 - s11), 0.f), 1.f);
        r1.z = fminf(fmaxf(s12 + f * (v12 - s12), 0.f), 1.f);
    } else {
        r0 = sharp3x3(img, f, x, y);
        r1 = sharp3x3(img, f, x, y + 1);
    }
}

// ---------------------------------------------------------------------------
// quad-row sharpness (pass2)
// ---------------------------------------------------------------------------
__device__ __forceinline__ void sharp4(const float* __restrict__ img,
                                       float f, int x, int y, F3 r[4])
{
    if (x >= 1 && x <= IMG_W - 2 && y >= 1 && y + 4 <= IMG_H - 1) {
        const float* base = img + ((size_t)(y - 1) * IMG_W + x) * 3;
        float out[4][3];
        #pragma unroll
        for (int ch = 0; ch < 3; ch++) {
            float R[6], V[6];
            #pragma unroll
            for (int j = 0; j < 6; j++) {
                const float* p = base + (size_t)j * ROWF;
                float l = p[ch - 3], c = p[ch], rr = p[ch + 3];
                V[j] = c;
                R[j] = l + c + rr;
            }
            #pragma unroll
            for (int i = 0; i < 4; i++) {
                float v = V[i + 1];
                float s = (R[i] + R[i+1] + R[i+2] + 4.f * v) * (1.f / 13.f);
                out[i][ch] = fminf(fmaxf(s + f * (v - s), 0.f), 1.f);
            }
        }
        #pragma unroll
        for (int i = 0; i < 4; i++) {
            r[i].x = out[i][0]; r[i].y = out[i][1]; r[i].z = out[i][2];
        }
    } else {
        #pragma unroll
        for (int i = 0; i < 4; i++) r[i] = sharp3x3(img, f, x, y + i);
    }
}

// ---------------------------------------------------------------------------
// dual-row gather dispatch (pass1)
// ---------------------------------------------------------------------------
__device__ __forceinline__ void apply_gather2(const float* __restrict__ img,
                                              int op, float s, int x, int y,
                                              F3& r0, F3& r1)
{
    const float cx = (IMG_W - 1) * 0.5f, cy = (IMG_H - 1) * 0.5f;
    const float xf  = (float)x - cx;
    const float yf0 = (float)y - cy;
    const float yf1 = (float)(y + 1) - cy;
    if (op == 0) {
        float th = s * 0.2617993877991494f;
        float co = cosf(th), si = sinf(th);
        r0 = bilin4(img, co * xf + si * yf0 + cx, -si * xf + co * yf0 + cy);
        r1 = bilin4(img, co * xf + si * yf1 + cx, -si * xf + co * yf1 + cy);
    } else if (op == 1) {
        float sh = -s * 0.15f;
        r0 = bilin_h(img, xf + sh * yf0 + cx, y);
        r1 = bilin_h(img, xf + sh * yf1 + cx, y + 1);
    } else if (op == 2) {
        float sh = -s * 0.15f;
        bilin_v2(img, yf0 + sh * xf + cy, yf1 + sh * xf + cy, x, r0, r1);
    } else if (op == 3) {
        float t = -s * 0.15f * (float)IMG_W;
        float xi = xf + t + cx;
        r0 = bilin_h(img, xi, y);
        r1 = bilin_h(img, xi, y + 1);
    } else if (op == 4) {
        float t = -s * 0.15f * (float)IMG_H;
        bilin_v2(img, yf0 + t + cy, yf1 + t + cy, x, r0, r1);
    } else {
        float f = (s > 0.f) ? 1.45f : (1.0f / 1.45f);
        sharp2(img, f, x, y, r0, r1);
    }
}

// ---------------------------------------------------------------------------
// quad-row gather dispatch (pass2)
// ---------------------------------------------------------------------------
__device__ __forceinline__ void apply_gather4(const float* __restrict__ img,
                                              int op, float s, int x, int y,
                                              F3 r[4])
{
    const float cx = (IMG_W - 1) * 0.5f, cy = (IMG_H - 1) * 0.5f;
    const float xf = (float)x - cx;
    float yf[4];
    #pragma unroll
    for (int i = 0; i < 4; i++) yf[i] = (float)(y + i) - cy;

    if (op == 0) {
        float th = s * 0.2617993877991494f;
        float co = cosf(th), si = sinf(th);
        #pragma unroll
        for (int i = 0; i < 4; i++)
            r[i] = bilin4(img, co * xf + si * yf[i] + cx,
                               -si * xf + co * yf[i] + cy);
    } else if (op == 1) {
        float sh = -s * 0.15f;
        #pragma unroll
        for (int i = 0; i < 4; i++)
            r[i] = bilin_h(img, xf + sh * yf[i] + cx, y + i);
    } else if (op == 2) {
        float sh = -s * 0.15f;
        float yi[4];
        #pragma unroll
        for (int i = 0; i < 4; i++) yi[i] = yf[i] + sh * xf + cy;
        bilin_v4(img, yi, x, r);
    } else if (op == 3) {
        float t = -s * 0.15f * (float)IMG_W;
        float xi = xf + t + cx;
        #pragma unroll
        for (int i = 0; i < 4; i++)
            r[i] = bilin_h(img, xi, y + i);
    } else if (op == 4) {
        float t = -s * 0.15f * (float)IMG_H;
        float yi[4];
        #pragma unroll
        for (int i = 0; i < 4; i++) yi[i] = yf[i] + t + cy;
        bilin_v4(img, yi, x, r);
    } else {
        float f = (s > 0.f) ? 1.45f : (1.0f / 1.45f);
        sharp4(img, f, x, y, r);
    }
}

// ---------------------------------------------------------------------------
// reduce0: per-image partial sums of original (only op0 == contrast)
// ---------------------------------------------------------------------------
__global__ void reduce0_kernel(const float* __restrict__ in,
                               const int* __restrict__ op_ids)
{
    int b = blockIdx.y;
    if (op_ids[b * 2] != 6) return;
    const float4* img = (const float4*)(in + (size_t)b * NPEL);
    float s = 0.f;
    for (int i = blockIdx.x * 256 + threadIdx.x; i < NPEL / 4; i += RBLK * 256) {
        float4 v = img[i];
        s += v.x + v.y + v.z + v.w;
    }
    __shared__ float sd[256];
    sd[threadIdx.x] = s;
    __syncthreads();
    #pragma unroll
    for (int st = 128; st > 0; st >>= 1) {
        if (threadIdx.x < st) sd[threadIdx.x] += sd[threadIdx.x + st];
        __syncthreads();
    }
    if (threadIdx.x == 0) g_partial0[b * RBLK + blockIdx.x] = sd[0];
}

// ---------------------------------------------------------------------------
// combine1: fold pass1's per-block partials (P1BLK per image) -> g_mean1[b]
// ---------------------------------------------------------------------------
__global__ void combine1_kernel(const int* __restrict__ op_ids)
{
    int b = blockIdx.x;
    if (op_ids[b * 2 + 1] != 6) return;
    __shared__ float sd[256];
    float s = g_partial1[b * P1BLK + threadIdx.x]
            + g_partial1[b * P1BLK + 256 + threadIdx.x];
    sd[threadIdx.x] = s;
    __syncthreads();
    #pragma unroll
    for (int st = 128; st > 0; st >>= 1) {
        if (threadIdx.x < st) sd[threadIdx.x] += sd[threadIdx.x + st];
        __syncthreads();
    }
    if (threadIdx.x == 0) g_mean1[b] = sd[0] * (1.0f / (float)NPEL);
}

// ---------------------------------------------------------------------------
// pass1: layer 0. Grid = P1BLK blocks/image (no idle blocks).
//  - pointwise op0: grid-stride float4 streaming (coalesced).
//  - gather op0: dual-row, thread = 2 pixels.
// op1==brightness fused inline -> out, else -> scratch.
// If op1==contrast: block-partial sums of the intermediate -> g_partial1.
// ---------------------------------------------------------------------------
__global__ void pass1_kernel(const float* __restrict__ in,
                             float* __restrict__ out,
                             const int* __restrict__ op_ids,
                             const int* __restrict__ signs)
{
    const int b   = blockIdx.z;
    const int idx = blockIdx.x * blockDim.x + threadIdx.x;   // [0, NPIX/2)

    const int op0 = op_ids[b * 2], op1 = op_ids[b * 2 + 1];
    const float s0 = signs[b * 2]     ? 1.f : -1.f;
    const float s1 = signs[b * 2 + 1] ? 1.f : -1.f;
    const bool  fuse_b   = (op1 == 5);
    const bool  need_sum = (op1 == 6);
    const float f1 = (s1 > 0.f) ? 1.45f : (1.0f / 1.45f);

    const float* img = in + (size_t)b * NPEL;
    float* dstbase = (fuse_b ? out : g_scratch) + (size_t)b * NPEL;

    float acc = 0.f;

    if (op0 == 5 || op0 == 6) {                 // pointwise: float4 streaming
        const float f0 = (s0 > 0.f) ? 1.45f : (1.0f / 1.45f);
        const float m0 = (op0 == 6) ? inline_mean(g_partial0, b) : 0.f;
        for (int i = idx; i < NPEL / 4; i += P1BLK * 256) {
            float4 v = ((const float4*)img)[i];
            float t[4] = { v.x, v.y, v.z, v.w };
            #pragma unroll
            for (int k = 0; k < 4; k++) {
                float u = (op0 == 5) ? f0 * t[k] : m0 + f0 * (t[k] - m0);
                t[k] = fminf(fmaxf(u, 0.f), 1.f);
            }
            if (fuse_b) {
                #pragma unroll
                for (int k = 0; k < 4; k++)
                    t[k] = fminf(fmaxf(f1 * t[k], 0.f), 1.f);
            }
            if (need_sum) acc += t[0] + t[1] + t[2] + t[3];
            ((float4*)dstbase)[i] = make_float4(t[0], t[1], t[2], t[3]);
        }
    } else {
        // gather path: dual-row, all threads active
        const int y = (idx >> 9) * 2;
        const int x = idx & (IMG_W - 1);

        F3 r0, r1;
        apply_gather2(img, op0, s0, x, y, r0, r1);

        if (fuse_b) {
            r0.x = fminf(fmaxf(f1 * r0.x, 0.f), 1.f);
            r0.y = fminf(fmaxf(f1 * r0.y, 0.f), 1.f);
            r0.z = fminf(fmaxf(f1 * r0.z, 0.f), 1.f);
            r1.x = fminf(fmaxf(f1 * r1.x, 0.f), 1.f);
            r1.y = fminf(fmaxf(f1 * r1.y, 0.f), 1.f);
            r1.z = fminf(fmaxf(f1 * r1.z, 0.f), 1.f);
        }
        if (need_sum)
            acc = r0.x + r0.y + r0.z + r1.x + r1.y + r1.z;

        float* o0 = dstbase + ((size_t)y * IMG_W + x) * 3;
        float* o1 = o0 + ROWF;
        o0[0] = r0.x; o0[1] = r0.y; o0[2] = r0.z;
        o1[0] = r1.x; o1[1] = r1.y; o1[2] = r1.z;
    }

    if (need_sum) {                             // image-uniform branch
        __shared__ float sd[256];
        sd[threadIdx.x] = acc;
        __syncthreads();
        #pragma unroll
        for (int st = 128; st > 0; st >>= 1) {
            if (threadIdx.x < st) sd[threadIdx.x] += sd[threadIdx.x + st];
            __syncthreads();
        }
        if (threadIdx.x == 0) g_partial1[b * P1BLK + blockIdx.x] = sd[0];
    }
}

// ---------------------------------------------------------------------------
// pass2: layer 1 from scratch -> out. Grid = NPIX/4/256 blocks (no idle).
//  - contrast: grid-stride float4 streaming with g_mean1.
//  - gather: quad-row.
// ---------------------------------------------------------------------------
__global__ void pass2_kernel(float* __restrict__ out,
                             const int* __restrict__ op_ids,
                             const int* __restrict__ signs)
{
    const int b   = blockIdx.z;
    const int op1 = op_ids[b * 2 + 1];
    if (op1 == 5) return;                       // fused into pass1

    const int idx = blockIdx.x * blockDim.x + threadIdx.x;   // [0, NPIX/4)
    const float s1 = signs[b * 2 + 1] ? 1.f : -1.f;
    const float f1 = (s1 > 0.f) ? 1.45f : (1.0f / 1.45f);

    const float* img = g_scratch + (size_t)b * NPEL;
    float* outb = out + (size_t)b * NPEL;

    if (op1 == 6) {                             // contrast: float4 streaming
        const float m = g_mean1[b];
        for (int i = idx; i < NPEL / 4; i += NPIX / 4) {
            float4 v = ((const float4*)img)[i];
            float t[4] = { v.x, v.y, v.z, v.w };
            #pragma unroll
            for (int k = 0; k < 4; k++)
                t[k] = fminf(fmaxf(m + f1 * (t[k] - m), 0.f), 1.f);
            ((float4*)outb)[i] = make_float4(t[0], t[1], t[2], t[3]);
        }
        return;
    }

    // gather path: quad-row, all threads active
    const int y = (idx >> 9) * 4;
    const int x = idx & (IMG_W - 1);

    F3 r[4];
    apply_gather4(img, op1, s1, x, y, r);

    float* o = outb + ((size_t)y * IMG_W + x) * 3;
    #pragma unroll
    for (int i = 0; i < 4; i++) {
        o[0] = r[i].x; o[1] = r[i].y; o[2] = r[i].z;
        o += ROWF;
    }
}

// ---------------------------------------------------------------------------
extern "C" void kernel_launch(void* const* d_in, const int* in_sizes, int n_in,
                              void* d_out, int out_size)
{
    const float* images = (const float*)d_in[0];
    const int*   op_ids = (const int*)  d_in[1];
    const int*   signs  = (const int*)  d_in[2];
    float*       out    = (float*)d_out;

    dim3 rgrid(RBLK, NB);
    dim3 g1(P1BLK, 1, NB);            // 512 blocks/image
    dim3 g2(NPIX / 4 / 256, 1, NB);   // 256 blocks/image

    reduce0_kernel <<<rgrid, 256>>>(images, op_ids);
    pass1_kernel   <<<g1, 256>>>(images, out, op_ids, signs);
    combine1_kernel<<<NB, 256>>>(op_ids);
    pass2_kernel   <<<g2, 256>>>(out, op_ids, signs);
}

// round 13
// speedup vs baseline: 1.1755x; 1.0375x over previous
#include <cuda_runtime.h>
#include <math.h>

#define IMG_H 512
#define IMG_W 512
#define NB    64
#define NPIX  (IMG_H * IMG_W)
#define NPEL  (NPIX * 3)
#define RBLK  64
#define ROWF  (IMG_W * 3)
#define P1BLK 256          // pass1 blocks per image (= NPIX/4/256)

__device__ float g_scratch[(size_t)NB * NPEL];
__device__ float g_partial0[NB * RBLK];
__device__ float g_partial1[NB * P1BLK];
__device__ float g_mean1[NB];

struct F3 { float x, y, z; };

__device__ __forceinline__ float inline_mean(const float* __restrict__ part, int b)
{
    float s = 0.f;
    #pragma unroll
    for (int i = 0; i < RBLK; i++) s += part[b * RBLK + i];
    return s * (1.0f / (float)NPEL);
}

// ---------------------------------------------------------------------------
// horizontal 2-tap bilinear (wy == 0 exactly)
// ---------------------------------------------------------------------------
__device__ __forceinline__ F3 bilin_h(const float* __restrict__ img, float xi, int y)
{
    float x0f = floorf(xi);
    float wx  = xi - x0f;
    float w0  = 1.f - wx;
    int   x0  = (int)x0f;
    const float* row = img + (size_t)y * ROWF;
    F3 r;
    if (x0 >= 0 && x0 < IMG_W - 1) {
        const float* p = row + x0 * 3;
        r.x = w0 * p[0] + wx * p[3];
        r.y = w0 * p[1] + wx * p[4];
        r.z = w0 * p[2] + wx * p[5];
    } else {
        bool v0 = (x0 >= 0)  && (x0 <= IMG_W - 1);
        bool v1 = (x0 >= -1) && (x0 <= IMG_W - 2);
        int xc0 = min(max(x0,     0), IMG_W - 1);
        int xc1 = min(max(x0 + 1, 0), IMG_W - 1);
        const float* p0 = row + xc0 * 3;
        const float* p1 = row + xc1 * 3;
        float a0 = v0 ? p0[0] : 0.5f, a1 = v0 ? p0[1] : 0.5f, a2 = v0 ? p0[2] : 0.5f;
        float b0 = v1 ? p1[0] : 0.5f, b1 = v1 ? p1[1] : 0.5f, b2 = v1 ? p1[2] : 0.5f;
        r.x = w0 * a0 + wx * b0;
        r.y = w0 * a1 + wx * b1;
        r.z = w0 * a2 + wx * b2;
    }
    return r;
}

// ---------------------------------------------------------------------------
// vertical 2-tap bilinear, single output (border/fallback)
// ---------------------------------------------------------------------------
__device__ __forceinline__ F3 bilin_v(const float* __restrict__ img, float yi, int x)
{
    float y0f = floorf(yi);
    float wy  = yi - y0f;
    float w0  = 1.f - wy;
    int   y0  = (int)y0f;
    F3 r;
    if (y0 >= 0 && y0 < IMG_H - 1) {
        const float* p = img + ((size_t)y0 * IMG_W + x) * 3;
        const float* q = p + ROWF;
        r.x = w0 * p[0] + wy * q[0];
        r.y = w0 * p[1] + wy * q[1];
        r.z = w0 * p[2] + wy * q[2];
    } else {
        bool v0 = (y0 >= 0)  && (y0 <= IMG_H - 1);
        bool v1 = (y0 >= -1) && (y0 <= IMG_H - 2);
        int yc0 = min(max(y0,     0), IMG_H - 1);
        int yc1 = min(max(y0 + 1, 0), IMG_H - 1);
        const float* p0 = img + ((size_t)yc0 * IMG_W + x) * 3;
        const float* p1 = img + ((size_t)yc1 * IMG_W + x) * 3;
        float a0 = v0 ? p0[0] : 0.5f, a1 = v0 ? p0[1] : 0.5f, a2 = v0 ? p0[2] : 0.5f;
        float b0 = v1 ? p1[0] : 0.5f, b1 = v1 ? p1[1] : 0.5f, b2 = v1 ? p1[2] : 0.5f;
        r.x = w0 * a0 + wy * b0;
        r.y = w0 * a1 + wy * b1;
        r.z = w0 * a2 + wy * b2;
    }
    return r;
}

// ---------------------------------------------------------------------------
// quad-row vertical bilinear: 5 tap rows for 4 outputs when aligned
// ---------------------------------------------------------------------------
__device__ __forceinline__ void bilin_v4(const float* __restrict__ img,
                                         const float yi[4], int x, F3 r[4])
{
    float k0f = floorf(yi[0]);
    int   k0  = (int)k0f;
    bool aligned = (k0 >= 0) && (k0 + 4 <= IMG_H - 1);
    #pragma unroll
    for (int i = 1; i < 4; i++)
        aligned = aligned && ((int)floorf(yi[i]) == k0 + i);
    if (aligned) {
        const float* p = img + ((size_t)k0 * IMG_W + x) * 3;
        float rv[5][3];
        #pragma unroll
        for (int j = 0; j < 5; j++) {
            rv[j][0] = p[0]; rv[j][1] = p[1]; rv[j][2] = p[2];
            p += ROWF;
        }
        #pragma unroll
        for (int i = 0; i < 4; i++) {
            float wy = yi[i] - floorf(yi[i]);
            float w0 = 1.f - wy;
            r[i].x = w0 * rv[i][0] + wy * rv[i+1][0];
            r[i].y = w0 * rv[i][1] + wy * rv[i+1][1];
            r[i].z = w0 * rv[i][2] + wy * rv[i+1][2];
        }
    } else {
        #pragma unroll
        for (int i = 0; i < 4; i++) r[i] = bilin_v(img, yi[i], x);
    }
}

// ---------------------------------------------------------------------------
// general 4-tap bilinear (rotate)
// ---------------------------------------------------------------------------
__device__ __forceinline__ F3 bilin4(const float* __restrict__ img, float xi, float yi)
{
    float x0f = floorf(xi), y0f = floorf(yi);
    float wx = xi - x0f,    wy = yi - y0f;
    int   x0 = (int)x0f,    y0 = (int)y0f;
    float w00 = (1.f - wx) * (1.f - wy);
    float w10 = wx * (1.f - wy);
    float w01 = (1.f - wx) * wy;
    float w11 = wx * wy;
    F3 r;
    if (x0 >= 0 && x0 < IMG_W - 1 && y0 >= 0 && y0 < IMG_H - 1) {
        const float* p = img + ((size_t)y0 * IMG_W + x0) * 3;
        const float* q = p + ROWF;
        r.x = w00 * p[0] + w10 * p[3] + w01 * q[0] + w11 * q[3];
        r.y = w00 * p[1] + w10 * p[4] + w01 * q[1] + w11 * q[4];
        r.z = w00 * p[2] + w10 * p[5] + w01 * q[2] + w11 * q[5];
    } else {
        bool vx0 = (x0 >= 0)  && (x0 <= IMG_W - 1);
        bool vx1 = (x0 >= -1) && (x0 <= IMG_W - 2);
        bool vy0 = (y0 >= 0)  && (y0 <= IMG_H - 1);
        bool vy1 = (y0 >= -1) && (y0 <= IMG_H - 2);
        int xc0 = min(max(x0,     0), IMG_W - 1);
        int xc1 = min(max(x0 + 1, 0), IMG_W - 1);
        int yc0 = min(max(y0,     0), IMG_H - 1);
        int yc1 = min(max(y0 + 1, 0), IMG_H - 1);
        const float* p00 = img + ((size_t)yc0 * IMG_W + xc0) * 3;
        const float* p10 = img + ((size_t)yc0 * IMG_W + xc1) * 3;
        const float* p01 = img + ((size_t)yc1 * IMG_W + xc0) * 3;
        const float* p11 = img + ((size_t)yc1 * IMG_W + xc1) * 3;
        bool v00 = vx0 && vy0, v10 = vx1 && vy0, v01 = vx0 && vy1, v11 = vx1 && vy1;
        r.x = w00 * (v00 ? p00[0] : 0.5f) + w10 * (v10 ? p10[0] : 0.5f)
            + w01 * (v01 ? p01[0] : 0.5f) + w11 * (v11 ? p11[0] : 0.5f);
        r.y = w00 * (v00 ? p00[1] : 0.5f) + w10 * (v10 ? p10[1] : 0.5f)
            + w01 * (v01 ? p01[1] : 0.5f) + w11 * (v11 ? p11[1] : 0.5f);
        r.z = w00 * (v00 ? p00[2] : 0.5f) + w10 * (v10 ? p10[2] : 0.5f)
            + w01 * (v01 ? p01[2] : 0.5f) + w11 * (v11 ? p11[2] : 0.5f);
    }
    return r;
}

// ---------------------------------------------------------------------------
// single-pixel sharpness (border/fallback)
// ---------------------------------------------------------------------------
__device__ __forceinline__ F3 sharp3x3(const float* __restrict__ img,
                                       float f, int x, int y)
{
    const float* p = img + ((size_t)y * IMG_W + x) * 3;
    float v0 = p[0], v1 = p[1], v2 = p[2];
    float s0 = 0.f, s1 = 0.f, s2 = 0.f;
    #pragma unroll
    for (int dy = -1; dy <= 1; dy++) {
        int yy = min(max(y + dy, 0), IMG_H - 1);
        #pragma unroll
        for (int dx = -1; dx <= 1; dx++) {
            int xx = min(max(x + dx, 0), IMG_W - 1);
            float k = (dx == 0 && dy == 0) ? (5.0f/13.0f) : (1.0f/13.0f);
            const float* q = img + ((size_t)yy * IMG_W + xx) * 3;
            s0 += k * q[0]; s1 += k * q[1]; s2 += k * q[2];
        }
    }
    F3 r;
    r.x = fminf(fmaxf(s0 + f * (v0 - s0), 0.f), 1.f);
    r.y = fminf(fmaxf(s1 + f * (v1 - s1), 0.f), 1.f);
    r.z = fminf(fmaxf(s2 + f * (v2 - s2), 0.f), 1.f);
    return r;
}

// ---------------------------------------------------------------------------
// quad-row sharpness: 6 kernel rows (18 taps) for 4 outputs, channel-major
// ---------------------------------------------------------------------------
__device__ __forceinline__ void sharp4(const float* __restrict__ img,
                                       float f, int x, int y, F3 r[4])
{
    if (x >= 1 && x <= IMG_W - 2 && y >= 1 && y + 4 <= IMG_H - 1) {
        const float* base = img + ((size_t)(y - 1) * IMG_W + x) * 3;
        float out[4][3];
        #pragma unroll
        for (int ch = 0; ch < 3; ch++) {
            float R[6], V[6];
            #pragma unroll
            for (int j = 0; j < 6; j++) {
                const float* p = base + (size_t)j * ROWF;
                float l = p[ch - 3], c = p[ch], rr = p[ch + 3];
                V[j] = c;
                R[j] = l + c + rr;
            }
            #pragma unroll
            for (int i = 0; i < 4; i++) {
                float v = V[i + 1];
                float s = (R[i] + R[i+1] + R[i+2] + 4.f * v) * (1.f / 13.f);
                out[i][ch] = fminf(fmaxf(s + f * (v - s), 0.f), 1.f);
            }
        }
        #pragma unroll
        for (int i = 0; i < 4; i++) {
            r[i].x = out[i][0]; r[i].y = out[i][1]; r[i].z = out[i][2];
        }
    } else {
        #pragma unroll
        for (int i = 0; i < 4; i++) r[i] = sharp3x3(img, f, x, y + i);
    }
}

// ---------------------------------------------------------------------------
// quad-row gather dispatch; op image-uniform, pixels (x, y..y+3)
// ---------------------------------------------------------------------------
__device__ __forceinline__ void apply_gather4(const float* __restrict__ img,
                                              int op, float s, int x, int y,
                                              F3 r[4])
{
    const float cx = (IMG_W - 1) * 0.5f, cy = (IMG_H - 1) * 0.5f;
    const float xf = (float)x - cx;
    float yf[4];
    #pragma unroll
    for (int i = 0; i < 4; i++) yf[i] = (float)(y + i) - cy;

    if (op == 0) {
        float th = s * 0.2617993877991494f;
        float co = cosf(th), si = sinf(th);
        #pragma unroll
        for (int i = 0; i < 4; i++)
            r[i] = bilin4(img, co * xf + si * yf[i] + cx,
                               -si * xf + co * yf[i] + cy);
    } else if (op == 1) {
        float sh = -s * 0.15f;
        #pragma unroll
        for (int i = 0; i < 4; i++)
            r[i] = bilin_h(img, xf + sh * yf[i] + cx, y + i);
    } else if (op == 2) {
        float sh = -s * 0.15f;
        float yi[4];
        #pragma unroll
        for (int i = 0; i < 4; i++) yi[i] = yf[i] + sh * xf + cy;
        bilin_v4(img, yi, x, r);
    } else if (op == 3) {
        float t = -s * 0.15f * (float)IMG_W;
        float xi = xf + t + cx;
        #pragma unroll
        for (int i = 0; i < 4; i++)
            r[i] = bilin_h(img, xi, y + i);
    } else if (op == 4) {
        float t = -s * 0.15f * (float)IMG_H;
        float yi[4];
        #pragma unroll
        for (int i = 0; i < 4; i++) yi[i] = yf[i] + t + cy;
        bilin_v4(img, yi, x, r);
    } else {
        float f = (s > 0.f) ? 1.45f : (1.0f / 1.45f);
        sharp4(img, f, x, y, r);
    }
}

// ---------------------------------------------------------------------------
// reduce0: per-image partial sums of original (only op0 == contrast)
// ---------------------------------------------------------------------------
__global__ void reduce0_kernel(const float* __restrict__ in,
                               const int* __restrict__ op_ids)
{
    int b = blockIdx.y;
    if (op_ids[b * 2] != 6) return;
    const float4* img = (const float4*)(in + (size_t)b * NPEL);
    float s = 0.f;
    for (int i = blockIdx.x * 256 + threadIdx.x; i < NPEL / 4; i += RBLK * 256) {
        float4 v = img[i];
        s += v.x + v.y + v.z + v.w;
    }
    __shared__ float sd[256];
    sd[threadIdx.x] = s;
    __syncthreads();
    #pragma unroll
    for (int st = 128; st > 0; st >>= 1) {
        if (threadIdx.x < st) sd[threadIdx.x] += sd[threadIdx.x + st];
        __syncthreads();
    }
    if (threadIdx.x == 0) g_partial0[b * RBLK + blockIdx.x] = sd[0];
}

// ---------------------------------------------------------------------------
// combine1: fold pass1's per-block partials (P1BLK per image) -> g_mean1[b]
// ---------------------------------------------------------------------------
__global__ void combine1_kernel(const int* __restrict__ op_ids)
{
    int b = blockIdx.x;
    if (op_ids[b * 2 + 1] != 6) return;
    __shared__ float sd[256];
    sd[threadIdx.x] = g_partial1[b * P1BLK + threadIdx.x];
    __syncthreads();
    #pragma unroll
    for (int st = 128; st > 0; st >>= 1) {
        if (threadIdx.x < st) sd[threadIdx.x] += sd[threadIdx.x + st];
        __syncthreads();
    }
    if (threadIdx.x == 0) g_mean1[b] = sd[0] * (1.0f / (float)NPEL);
}

// ---------------------------------------------------------------------------
// pass1: layer 0. Grid = P1BLK blocks/image (no idle blocks).
//  - pointwise op0: grid-stride float4 streaming (coalesced).
//  - gather op0: quad-row, thread = 4 pixels.
// op1==brightness fused inline -> out, else -> scratch.
// If op1==contrast: block-partial sums of the intermediate -> g_partial1.
// ---------------------------------------------------------------------------
__global__ void pass1_kernel(const float* __restrict__ in,
                             float* __restrict__ out,
                             const int* __restrict__ op_ids,
                             const int* __restrict__ signs)
{
    const int b   = blockIdx.z;
    const int idx = blockIdx.x * blockDim.x + threadIdx.x;   // [0, NPIX/4)

    const int op0 = op_ids[b * 2], op1 = op_ids[b * 2 + 1];
    const float s0 = signs[b * 2]     ? 1.f : -1.f;
    const float s1 = signs[b * 2 + 1] ? 1.f : -1.f;
    const bool  fuse_b   = (op1 == 5);
    const bool  need_sum = (op1 == 6);
    const float f1 = (s1 > 0.f) ? 1.45f : (1.0f / 1.45f);

    const float* img = in + (size_t)b * NPEL;
    float* dstbase = (fuse_b ? out : g_scratch) + (size_t)b * NPEL;

    float acc = 0.f;

    if (op0 == 5 || op0 == 6) {                 // pointwise: float4 streaming
        const float f0 = (s0 > 0.f) ? 1.45f : (1.0f / 1.45f);
        const float m0 = (op0 == 6) ? inline_mean(g_partial0, b) : 0.f;
        for (int i = idx; i < NPEL / 4; i += P1BLK * 256) {
            float4 v = ((const float4*)img)[i];
            float t[4] = { v.x, v.y, v.z, v.w };
            #pragma unroll
            for (int k = 0; k < 4; k++) {
                float u = (op0 == 5) ? f0 * t[k] : m0 + f0 * (t[k] - m0);
                t[k] = fminf(fmaxf(u, 0.f), 1.f);
            }
            if (fuse_b) {
                #pragma unroll
                for (int k = 0; k < 4; k++)
                    t[k] = fminf(fmaxf(f1 * t[k], 0.f), 1.f);
            }
            if (need_sum) acc += t[0] + t[1] + t[2] + t[3];
            ((float4*)dstbase)[i] = make_float4(t[0], t[1], t[2], t[3]);
        }
    } else {
        // gather path: quad-row, all threads active
        const int y = (idx >> 9) * 4;
        const int x = idx & (IMG_W - 1);

        F3 r[4];
        apply_gather4(img, op0, s0, x, y, r);

        if (fuse_b) {
            #pragma unroll
            for (int i = 0; i < 4; i++) {
                r[i].x = fminf(fmaxf(f1 * r[i].x, 0.f), 1.f);
                r[i].y = fminf(fmaxf(f1 * r[i].y, 0.f), 1.f);
                r[i].z = fminf(fmaxf(f1 * r[i].z, 0.f), 1.f);
            }
        }
        if (need_sum) {
            #pragma unroll
            for (int i = 0; i < 4; i++)
                acc += r[i].x + r[i].y + r[i].z;
        }

        float* o = dstbase + ((size_t)y * IMG_W + x) * 3;
        #pragma unroll
        for (int i = 0; i < 4; i++) {
            o[0] = r[i].x; o[1] = r[i].y; o[2] = r[i].z;
            o += ROWF;
        }
    }

    if (need_sum) {                             // image-uniform branch
        __shared__ float sd[256];
        sd[threadIdx.x] = acc;
        __syncthreads();
        #pragma unroll
        for (int st = 128; st > 0; st >>= 1) {
            if (threadIdx.x < st) sd[threadIdx.x] += sd[threadIdx.x + st];
            __syncthreads();
        }
        if (threadIdx.x == 0) g_partial1[b * P1BLK + blockIdx.x] = sd[0];
    }
}

// ---------------------------------------------------------------------------
// pass2: layer 1 from scratch -> out. Grid = NPIX/4/256 blocks (no idle).
//  - contrast: grid-stride float4 streaming with g_mean1.
//  - gather: quad-row.
// ---------------------------------------------------------------------------
__global__ void pass2_kernel(float* __restrict__ out,
                             const int* __restrict__ op_ids,
                             const int* __restrict__ signs)
{
    const int b   = blockIdx.z;
    const int op1 = op_ids[b * 2 + 1];
    if (op1 == 5) return;                       // fused into pass1

    const int idx = blockIdx.x * blockDim.x + threadIdx.x;   // [0, NPIX/4)
    const float s1 = signs[b * 2 + 1] ? 1.f : -1.f;
    const float f1 = (s1 > 0.f) ? 1.45f : (1.0f / 1.45f);

    const float* img = g_scratch + (size_t)b * NPEL;
    float* outb = out + (size_t)b * NPEL;

    if (op1 == 6) {                             // contrast: float4 streaming
        const float m = g_mean1[b];
        for (int i = idx; i < NPEL / 4; i += NPIX / 4) {
            float4 v = ((const float4*)img)[i];
            float t[4] = { v.x, v.y, v.z, v.w };
            #pragma unroll
            for (int k = 0; k < 4; k++)
                t[k] = fminf(fmaxf(m + f1 * (t[k] - m), 0.f), 1.f);
            ((float4*)outb)[i] = make_float4(t[0], t[1], t[2], t[3]);
        }
        return;
    }

    // gather path: quad-row, all threads active
    const int y = (idx >> 9) * 4;
    const int x = idx & (IMG_W - 1);

    F3 r[4];
    apply_gather4(img, op1, s1, x, y, r);

    float* o = outb + ((size_t)y * IMG_W + x) * 3;
    #pragma unroll
    for (int i = 0; i < 4; i++) {
        o[0] = r[i].x; o[1] = r[i].y; o[2] = r[i].z;
        o += ROWF;
    }
}

// ---------------------------------------------------------------------------
extern "C" void kernel_launch(void* const* d_in, const int* in_sizes, int n_in,
                              void* d_out, int out_size)
{
    const float* images = (const float*)d_in[0];
    const int*   op_ids = (const int*)  d_in[1];
    const int*   signs  = (const int*)  d_in[2];
    float*       out    = (float*)d_out;

    dim3 rgrid(RBLK, NB);
    dim3 g1(P1BLK, 1, NB);            // 256 blocks/image
    dim3 g2(NPIX / 4 / 256, 1, NB);   // 256 blocks/image

    reduce0_kernel <<<rgrid, 256>>>(images, op_ids);
    pass1_kernel   <<<g1, 256>>>(images, out, op_ids, signs);
    combine1_kernel<<<NB, 256>>>(op_ids);
    pass2_kernel   <<<g2, 256>>>(out, op_ids, signs);
}